// round 6
// baseline (speedup 1.0000x reference)
#include <cuda_runtime.h>
#include <cuda_bf16.h>
#include <cstdint>

#define T_STEPS 2048
#define BATCH   16
#define DIM     1024
#define M_TOT   (T_STEPS * BATCH)   // 32768
#define EPS     1e-6f

// ---------------- GEMM tiling (unchanged, validated R5) ----------------
#define BM 128
#define BN 128
#define BK 32
#define NCHUNK 96
#define NSTAGES 4

#define RSTR 80
#define MATB (128 * RSTR)
#define OFF_A 0
#define OFF_B MATB
#define STG   (2 * MATB)
#define SMEM_TOTAL (NSTAGES * STG)  // 81920

// ---------------- scan config ----------------
#define SC_THREADS 128
#define SC_ELEMS   8               // per thread (128*8 = 1024 = DIM)
#define SC_DEPTH   8               // cp.async ring stages
#define SC_STAGE_F (SC_THREADS * SC_ELEMS)          // 1024 floats/stage
#define SC_RING_B  (SC_DEPTH * SC_STAGE_F * 4)      // 32768 bytes per array
#define SC_RED_OFF (2 * SC_RING_B)                  // 65536
#define SC_SMEM    (SC_RED_OFF + 4 * 5 * 4 * 4)     // + red[4][5][4]

// ---------------- scratch ----------------
__device__ __nv_bfloat16 g_xhi[(size_t)M_TOT * DIM];
__device__ __nv_bfloat16 g_xlo[(size_t)M_TOT * DIM];
__device__ __nv_bfloat16 g_whi[DIM * DIM], g_wlo[DIM * DIM];
__device__ __nv_bfloat16 g_vhi[DIM * DIM], g_vlo[DIM * DIM];
__device__ float g_wx[(size_t)M_TOT * DIM];
__device__ float g_gate[(size_t)M_TOT * DIM];

// ---------------- helpers ----------------
__device__ __forceinline__ uint32_t smem_u32(const void* p) {
    uint32_t a;
    asm("{ .reg .u64 t; cvta.to.shared.u64 t, %1; cvt.u32.u64 %0, t; }" : "=r"(a) : "l"(p));
    return a;
}
__device__ __forceinline__ void cpasync16(uint32_t dst, const void* src) {
    asm volatile("cp.async.cg.shared.global [%0], [%1], 16;" :: "r"(dst), "l"(src));
}
__device__ __forceinline__ void cp_commit() { asm volatile("cp.async.commit_group;"); }
__device__ __forceinline__ void cp_wait2()  { asm volatile("cp.async.wait_group 2;"); }
__device__ __forceinline__ void cp_wait3()  { asm volatile("cp.async.wait_group 3;"); }

__device__ __forceinline__ void ldm_x4(uint32_t& r0, uint32_t& r1, uint32_t& r2, uint32_t& r3,
                                       uint32_t addr) {
    asm volatile("ldmatrix.sync.aligned.m8n8.x4.shared.b16 {%0,%1,%2,%3}, [%4];"
                 : "=r"(r0), "=r"(r1), "=r"(r2), "=r"(r3) : "r"(addr));
}
__device__ __forceinline__ void mma16816(float* c, const uint32_t* a, const uint32_t* b) {
    asm volatile(
        "mma.sync.aligned.m16n8k16.row.col.f32.bf16.bf16.f32 "
        "{%0,%1,%2,%3}, {%4,%5,%6,%7}, {%8,%9}, {%0,%1,%2,%3};"
        : "+f"(c[0]), "+f"(c[1]), "+f"(c[2]), "+f"(c[3])
        : "r"(a[0]), "r"(a[1]), "r"(a[2]), "r"(a[3]), "r"(b[0]), "r"(b[1]));
}
__device__ __forceinline__ float sigmoidf_(float v) {
    return 1.0f / (1.0f + __expf(-v));
}

// ---------------- fp32 -> bf16 hi/lo split ----------------
__global__ __launch_bounds__(256)
void split_kernel(const float* __restrict__ s,
                  __nv_bfloat16* __restrict__ hi,
                  __nv_bfloat16* __restrict__ lo, int n4)
{
    int i = blockIdx.x * blockDim.x + threadIdx.x;
    if (i >= n4) return;
    float4 v = ((const float4*)s)[i];
    float a[4] = {v.x, v.y, v.z, v.w};
    __nv_bfloat16 h[4], l[4];
    #pragma unroll
    for (int j = 0; j < 4; j++) {
        h[j] = __float2bfloat16(a[j]);
        l[j] = __float2bfloat16(a[j] - __bfloat162float(h[j]));
    }
    ((__nv_bfloat162*)hi)[i * 2 + 0] = __nv_bfloat162(h[0], h[1]);
    ((__nv_bfloat162*)hi)[i * 2 + 1] = __nv_bfloat162(h[2], h[3]);
    ((__nv_bfloat162*)lo)[i * 2 + 0] = __nv_bfloat162(l[0], l[1]);
    ((__nv_bfloat162*)lo)[i * 2 + 1] = __nv_bfloat162(l[2], l[3]);
}

// ---------------- single-pass split-K GEMM (unchanged from R5) ----------------
__device__ __forceinline__ void load_chunk(uint32_t sbase,
                                           const __nv_bfloat16* __restrict__ Ap,
                                           const __nv_bfloat16* __restrict__ Bp,
                                           int kk)
{
    const int tid = threadIdx.x;
    #pragma unroll
    for (int j = 0; j < 2; j++) {
        int c   = tid + j * 256;
        int row = c >> 2;
        int cc  = c & 3;
        uint32_t so = (uint32_t)(row * RSTR + cc * 16);
        size_t   go = (size_t)row * DIM + kk + cc * 8;
        cpasync16(sbase + OFF_A + so, Ap + go);
        cpasync16(sbase + OFF_B + so, Bp + go);
    }
}

__global__ __launch_bounds__(256, 2)
void gemm_kernel(const __nv_bfloat16* __restrict__ xhi, const __nv_bfloat16* __restrict__ xlo,
                 const __nv_bfloat16* __restrict__ whi, const __nv_bfloat16* __restrict__ wlo,
                 const __nv_bfloat16* __restrict__ vhi, const __nv_bfloat16* __restrict__ vlo,
                 const float* __restrict__ bias0, const float* __restrict__ bias1,
                 float* __restrict__ wx, float* __restrict__ gate)
{
    extern __shared__ char smem[];
    const uint32_t sb = smem_u32(smem);
    const int tid  = threadIdx.x;
    const int wid  = tid >> 5;
    const int lane = tid & 31;
    const int bn = blockIdx.x, bm = blockIdx.y, z = blockIdx.z;

    const __nv_bfloat16* Ah = xhi + (size_t)bm * BM * DIM;
    const __nv_bfloat16* Al = xlo + (size_t)bm * BM * DIM;
    const __nv_bfloat16* Bh = (z ? vhi : whi) + (size_t)bn * BN * DIM;
    const __nv_bfloat16* Bl = (z ? vlo : wlo) + (size_t)bn * BN * DIM;
    const float* bias = z ? bias1 : bias0;
    float* C = z ? gate : wx;

    const __nv_bfloat16* pa[3] = {Ah, Ah, Al};
    const __nv_bfloat16* pb[3] = {Bh, Bl, Bh};

    const int wm0 = (wid & 1) * 64;
    const int wn0 = (wid >> 1) * 32;

    const uint32_t a_lane = (uint32_t)((lane & 15) * RSTR + (lane >> 4) * 16);
    const int g = lane >> 3;
    const uint32_t b_lane = (uint32_t)(((g >> 1) * 8 + (lane & 7)) * RSTR + (g & 1) * 16);

    float acc[4][4][4];
    #pragma unroll
    for (int mi = 0; mi < 4; mi++)
        #pragma unroll
        for (int ni = 0; ni < 4; ni++)
            #pragma unroll
            for (int r = 0; r < 4; r++) acc[mi][ni][r] = 0.0f;

    #pragma unroll
    for (int p = 0; p < 3; p++) {
        load_chunk(sb + p * STG, pa[0], pb[0], p * BK);
        cp_commit();
    }

    for (int i = 0; i < NCHUNK; i++) {
        cp_wait2();
        __syncthreads();

        if (i + 3 < NCHUNK) {
            const int ni_ = i + 3;
            const int ph = ni_ >> 5;
            load_chunk(sb + (uint32_t)(ni_ & 3) * STG, pa[ph], pb[ph], (ni_ & 31) * BK);
        }
        cp_commit();

        const uint32_t stg = sb + (uint32_t)(i & 3) * STG;
        const uint32_t aBase = stg + OFF_A + (uint32_t)(wm0 * RSTR) + a_lane;
        const uint32_t bBase = stg + OFF_B + (uint32_t)(wn0 * RSTR) + b_lane;

        #pragma unroll
        for (int ks = 0; ks < 2; ks++) {
            const uint32_t ko = (uint32_t)(ks * 32);
            uint32_t aF[4][4], bF[4][2];
            #pragma unroll
            for (int mi = 0; mi < 4; mi++)
                ldm_x4(aF[mi][0], aF[mi][1], aF[mi][2], aF[mi][3],
                       aBase + (uint32_t)(mi * 16 * RSTR) + ko);
            #pragma unroll
            for (int p = 0; p < 2; p++)
                ldm_x4(bF[2*p][0], bF[2*p][1], bF[2*p+1][0], bF[2*p+1][1],
                       bBase + (uint32_t)(p * 16 * RSTR) + ko);
            #pragma unroll
            for (int mi = 0; mi < 4; mi++)
                #pragma unroll
                for (int ni = 0; ni < 4; ni++)
                    mma16816(acc[mi][ni], aF[mi], bF[ni]);
        }
        __syncthreads();
    }

    const int m_glob = bm * BM + wm0 + (lane >> 2);
    const int n_glob = bn * BN + wn0 + (lane & 3) * 2;

    float bv[4][2];
    #pragma unroll
    for (int ni = 0; ni < 4; ni++) {
        bv[ni][0] = __ldg(bias + n_glob + ni * 8);
        bv[ni][1] = __ldg(bias + n_glob + ni * 8 + 1);
    }

    #pragma unroll
    for (int mi = 0; mi < 4; mi++) {
        #pragma unroll
        for (int ni = 0; ni < 4; ni++) {
            float v0 = acc[mi][ni][0] + bv[ni][0];
            float v1 = acc[mi][ni][1] + bv[ni][1];
            float v2 = acc[mi][ni][2] + bv[ni][0];
            float v3 = acc[mi][ni][3] + bv[ni][1];
            if (z) { v0 = sigmoidf_(v0); v1 = sigmoidf_(v1);
                     v2 = sigmoidf_(v2); v3 = sigmoidf_(v3); }
            float* p0 = C + (size_t)(m_glob + mi * 16)     * DIM + n_glob + ni * 8;
            float* p1 = C + (size_t)(m_glob + mi * 16 + 8) * DIM + n_glob + ni * 8;
            *(float2*)p0 = make_float2(v0, v1);
            *(float2*)p1 = make_float2(v2, v3);
        }
    }
}

// ---------------- pipelined scan ----------------
// u_t kept unnormalized; S_t rebuilt from scalar recurrence anchored on the
// direct reduction A_{t-2} = ||u_{t-2}||^2 (2-step window, no drift).
// 5 reductions/step (A,E,F,G,H) consumed 2 steps later -> reduce latency off
// the critical path. cp.async ring, 6-step prefetch distance.
__global__ __launch_bounds__(SC_THREADS)
void scan_kernel(const float* __restrict__ h0,
                 const float* __restrict__ wx,
                 const float* __restrict__ gate,
                 float* __restrict__ out_o,
                 float* __restrict__ out_h)
{
    extern __shared__ char smem[];
    float* ring_g = (float*)smem;                       // [SC_DEPTH][1024]
    float* ring_w = (float*)(smem + SC_RING_B);         // [SC_DEPTH][1024]
    float* red    = (float*)(smem + SC_RED_OFF);        // [4][5][4]
    const uint32_t sb = smem_u32(smem);

    const int b    = blockIdx.x;
    const int tid  = threadIdx.x;
    const int lane = tid & 31;
    const int wid  = tid >> 5;
    const int base = b * DIM + tid * SC_ELEMS;          // global per-thread base
    const int tstride = BATCH * DIM;

    const uint32_t rgoff = (uint32_t)(tid * SC_ELEMS * 4);          // bytes in stage
    const uint32_t stB   = (uint32_t)(SC_STAGE_F * 4);              // 4096 B/stage

    // issue stage s (loads g,wx row for step s into ring slot s&7)
    auto issue = [&](int s) {
        const uint32_t so = (uint32_t)(s & (SC_DEPTH - 1)) * stB + rgoff;
        const float* gs = gate + (size_t)s * tstride + base;
        const float* ws = wx   + (size_t)s * tstride + base;
        cpasync16(sb + so,                gs);
        cpasync16(sb + so + 16,           gs + 4);
        cpasync16(sb + SC_RING_B + so,      ws);
        cpasync16(sb + SC_RING_B + so + 16, ws + 4);
    };

    // prologue: stages 0..5 in flight
    #pragma unroll
    for (int s = 0; s < 6; s++) { issue(s); cp_commit(); }

    // u = h0 ; emit h row 0
    float u[SC_ELEMS];
    {
        float4 a = *(const float4*)(h0 + base);
        float4 c = *(const float4*)(h0 + base + 4);
        u[0]=a.x; u[1]=a.y; u[2]=a.z; u[3]=a.w;
        u[4]=c.x; u[5]=c.y; u[6]=c.z; u[7]=c.w;
        *(float4*)(out_h + base)     = a;
        *(float4*)(out_h + base + 4) = c;
    }

    // p queue: p0 = p_t, p1 = p_{t+1}, p2 = p_{t+2}
    float p0[SC_ELEMS], p1[SC_ELEMS], p2[SC_ELEMS];
    cp_wait3();   // stages 0,1,2 complete (producer==consumer per thread, no bar)
    {
        #pragma unroll
        for (int s = 0; s < 3; s++) {
            float* dst = (s == 0) ? p0 : (s == 1) ? p1 : p2;
            const float* rg = ring_g + s * SC_STAGE_F + tid * SC_ELEMS;
            const float* rw = ring_w + s * SC_STAGE_F + tid * SC_ELEMS;
            float4 ga = *(const float4*)rg,  gb = *(const float4*)(rg + 4);
            float4 wa = *(const float4*)rw,  wb = *(const float4*)(rw + 4);
            dst[0]=ga.x*wa.x; dst[1]=ga.y*wa.y; dst[2]=ga.z*wa.z; dst[3]=ga.w*wa.w;
            dst[4]=gb.x*wb.x; dst[5]=gb.y*wb.y; dst[6]=gb.z*wb.z; dst[7]=gb.w*wb.w;
        }
    }

    float r1 = 1.0f, r2 = 1.0f;   // r_{t-1}, r_{t-2}
    float S1d = 0.0f;             // direct S_1 from warmup
    float Hprev = 0.0f;           // H_{t-3} carried scalar

    for (int t = 0; t < T_STEPS; t++) {
        if (t + 6 < T_STEPS) issue(t + 6);
        cp_commit();                          // always commit (group accounting)

        // u_t = r_{t-1} * u_{t-1} + p_t
        #pragma unroll
        for (int j = 0; j < SC_ELEMS; j++) u[j] = fmaf(r1, u[j], p0[j]);

        // partials: A=|u|^2, E=u.p1, F=u.p2, G=p1.p2, H=|p2|^2
        float v[5] = {0.f, 0.f, 0.f, 0.f, 0.f};
        #pragma unroll
        for (int j = 0; j < SC_ELEMS; j++) {
            v[0] = fmaf(u[j],  u[j],  v[0]);
            v[1] = fmaf(u[j],  p1[j], v[1]);
            v[2] = fmaf(u[j],  p2[j], v[2]);
            v[3] = fmaf(p1[j], p2[j], v[3]);
            v[4] = fmaf(p2[j], p2[j], v[4]);
        }
        // warp reduce all 5
        #pragma unroll
        for (int k = 0; k < 5; k++) {
            #pragma unroll
            for (int o = 16; o > 0; o >>= 1)
                v[k] += __shfl_xor_sync(0xffffffffu, v[k], o);
        }
        const int slot = t & 3;
        if (lane == 0) {
            #pragma unroll
            for (int k = 0; k < 5; k++) red[(slot * 5 + k) * 4 + wid] = v[k];
        }
        __syncthreads();

        // scalar chain
        float rt;
        if (t >= 2) {
            const int s2 = (t - 2) & 3;
            float val = 0.0f;
            if (lane < 20) val = red[(s2 * 5 + (lane >> 2)) * 4 + (lane & 3)];
            val += __shfl_xor_sync(0xffffffffu, val, 2);
            val += __shfl_xor_sync(0xffffffffu, val, 1);
            const float As = __shfl_sync(0xffffffffu, val, 0);
            const float Es = __shfl_sync(0xffffffffu, val, 4);
            const float Fs = __shfl_sync(0xffffffffu, val, 8);
            const float Gs = __shfl_sync(0xffffffffu, val, 12);
            const float Hs = __shfl_sync(0xffffffffu, val, 16);

            // S_{t-1}: anchored on direct A_{t-2}
            const float Sm1 = (t == 2) ? S1d
                            : fmaf(r2 * r2, As, fmaf(2.0f * r2, Es, Hprev));
            const float dUP = fmaf(r2, Fs, Gs);               // dot(u_{t-1}, p_t)
            const float St  = fmaf(r1 * r1, Sm1, fmaf(2.0f * r1, dUP, Hs));
            rt = rsqrtf(St * (1.0f / (float)DIM) + EPS);
            Hprev = Hs;
        } else {
            // warmup: immediate direct S_t from this step's A partials
            const float* rr = red + slot * 5 * 4;
            const float Sd = rr[0] + rr[1] + rr[2] + rr[3];
            rt = rsqrtf(Sd * (1.0f / (float)DIM) + EPS);
            if (t == 1) S1d = Sd;
        }

        // outputs: h = rt*u ; o = h^2 * sigmoid(h)
        {
            float h[SC_ELEMS], o[SC_ELEMS];
            #pragma unroll
            for (int j = 0; j < SC_ELEMS; j++) {
                h[j] = rt * u[j];
                o[j] = h[j] * h[j] * sigmoidf_(h[j]);
            }
            const int ob = t * tstride + base;
            *(float4*)(out_o + ob)     = make_float4(o[0], o[1], o[2], o[3]);
            *(float4*)(out_o + ob + 4) = make_float4(o[4], o[5], o[6], o[7]);
            *(float4*)(out_h + ob + tstride)     = make_float4(h[0], h[1], h[2], h[3]);
            *(float4*)(out_h + ob + tstride + 4) = make_float4(h[4], h[5], h[6], h[7]);
        }

        r2 = r1; r1 = rt;

        // advance p queue; load p_{t+3}
        #pragma unroll
        for (int j = 0; j < SC_ELEMS; j++) { p0[j] = p1[j]; p1[j] = p2[j]; }
        if (t + 3 < T_STEPS) {
            cp_wait3();   // stage t+3 complete (committed at t-3; 3 newer pending)
            const int s = (t + 3) & (SC_DEPTH - 1);
            const float* rg = ring_g + s * SC_STAGE_F + tid * SC_ELEMS;
            const float* rw = ring_w + s * SC_STAGE_F + tid * SC_ELEMS;
            float4 ga = *(const float4*)rg,  gb = *(const float4*)(rg + 4);
            float4 wa = *(const float4*)rw,  wb = *(const float4*)(rw + 4);
            p2[0]=ga.x*wa.x; p2[1]=ga.y*wa.y; p2[2]=ga.z*wa.z; p2[3]=ga.w*wa.w;
            p2[4]=gb.x*wb.x; p2[5]=gb.y*wb.y; p2[6]=gb.z*wb.z; p2[7]=gb.w*wb.w;
        } else {
            #pragma unroll
            for (int j = 0; j < SC_ELEMS; j++) p2[j] = 0.0f;
        }
    }
}

// ---------------- launch ----------------
extern "C" void kernel_launch(void* const* d_in, const int* in_sizes, int n_in,
                              void* d_out, int out_size)
{
    const float* x  = (const float*)d_in[0];
    const float* h0 = (const float*)d_in[1];
    const float* W  = (const float*)d_in[2];
    const float* Wg = (const float*)d_in[3];
    const float* b  = (const float*)d_in[4];
    const float* bg = (const float*)d_in[5];

    float* out   = (float*)d_out;
    float* out_o = out;
    float* out_h = out + (size_t)T_STEPS * BATCH * DIM;

    __nv_bfloat16 *xhi, *xlo, *whi, *wlo, *vhi, *vlo;
    float *wxp, *gtp;
    cudaGetSymbolAddress((void**)&xhi, g_xhi);
    cudaGetSymbolAddress((void**)&xlo, g_xlo);
    cudaGetSymbolAddress((void**)&whi, g_whi);
    cudaGetSymbolAddress((void**)&wlo, g_wlo);
    cudaGetSymbolAddress((void**)&vhi, g_vhi);
    cudaGetSymbolAddress((void**)&vlo, g_vlo);
    cudaGetSymbolAddress((void**)&wxp, g_wx);
    cudaGetSymbolAddress((void**)&gtp, g_gate);

    {
        int n4 = M_TOT * DIM / 4;
        split_kernel<<<n4 / 256, 256>>>(x, xhi, xlo, n4);
        int w4 = DIM * DIM / 4;
        split_kernel<<<w4 / 256, 256>>>(W,  whi, wlo, w4);
        split_kernel<<<w4 / 256, 256>>>(Wg, vhi, vlo, w4);
    }

    cudaFuncSetAttribute(gemm_kernel, cudaFuncAttributeMaxDynamicSharedMemorySize, SMEM_TOTAL);
    dim3 grid(DIM / BN, M_TOT / BM, 2);
    gemm_kernel<<<grid, 256, SMEM_TOTAL>>>(xhi, xlo, whi, wlo, vhi, vlo, b, bg, wxp, gtp);

    cudaFuncSetAttribute(scan_kernel, cudaFuncAttributeMaxDynamicSharedMemorySize, SC_SMEM);
    scan_kernel<<<BATCH, SC_THREADS, SC_SMEM>>>(h0, wxp, gtp, out_o, out_h);
}